// round 12
// baseline (speedup 1.0000x reference)
#include <cuda_runtime.h>
#include <cuda_bf16.h>
#include <math.h>
#include <stdint.h>

// Problem constants
#define BB 2
#define TT 2048
#define HH 2048
#define NHD 16
#define HDIM 128
#define MM (BB*TT)      // 4096 token rows
#define FF (4*HH)       // 8192
#define H3 (3*HH)       // 6144

typedef unsigned short ushort_t;

// ---------------- scratch (device globals; allocation-free) ----------------
static __device__ ushort_t g_h_hi  [(size_t)MM*HH];
static __device__ ushort_t g_h_lo  [(size_t)MM*HH];
static __device__ ushort_t g_qkv_hi[(size_t)MM*H3];
static __device__ ushort_t g_qkv_lo[(size_t)MM*H3];
static __device__ ushort_t g_at_hi [(size_t)MM*HH];
static __device__ ushort_t g_at_lo [(size_t)MM*HH];
static __device__ ushort_t g_f_hi  [(size_t)MM*FF];
static __device__ ushort_t g_f_lo  [(size_t)MM*FF];
static __device__ float    g_x1    [(size_t)MM*HH];
// weight planes [K, N] row-major (B operand via ldmatrix.trans)
static __device__ ushort_t g_wqkv_hi[(size_t)HH*H3];
static __device__ ushort_t g_wqkv_lo[(size_t)HH*H3];
static __device__ ushort_t g_wo_hi[(size_t)HH*HH];
static __device__ ushort_t g_wo_lo[(size_t)HH*HH];
static __device__ ushort_t g_w1_hi[(size_t)HH*FF];
static __device__ ushort_t g_w1_lo[(size_t)HH*FF];
static __device__ ushort_t g_w2_hi[(size_t)HH*FF];
static __device__ ushort_t g_w2_lo[(size_t)HH*FF];

#define RS 0.08838834764831845f   // 1/sqrt(128)

// ---------------- helpers ----------------
__device__ __forceinline__ float gelu_tanh(float x) {
    float x3 = x * x * x;
    return 0.5f * x * (1.f + tanhf(0.7978845608028654f * (x + 0.044715f * x3)));
}
__device__ __forceinline__ uint32_t smem_u32(const void* p) {
    return (uint32_t)__cvta_generic_to_shared(p);
}
__device__ __forceinline__ void ldsm_x4(uint32_t* d, uint32_t addr) {
    asm volatile("ldmatrix.sync.aligned.m8n8.x4.shared.b16 {%0,%1,%2,%3}, [%4];"
                 : "=r"(d[0]), "=r"(d[1]), "=r"(d[2]), "=r"(d[3]) : "r"(addr));
}
__device__ __forceinline__ void ldsm_x4t(uint32_t* d, uint32_t addr) {
    asm volatile("ldmatrix.sync.aligned.m8n8.x4.trans.shared.b16 {%0,%1,%2,%3}, [%4];"
                 : "=r"(d[0]), "=r"(d[1]), "=r"(d[2]), "=r"(d[3]) : "r"(addr));
}
__device__ __forceinline__ void mma16816(float* c, const uint32_t* a, const uint32_t* b) {
    asm volatile("mma.sync.aligned.m16n8k16.row.col.f32.bf16.bf16.f32 "
                 "{%0,%1,%2,%3}, {%4,%5,%6,%7}, {%8,%9}, {%0,%1,%2,%3};"
                 : "+f"(c[0]), "+f"(c[1]), "+f"(c[2]), "+f"(c[3])
                 : "r"(a[0]), "r"(a[1]), "r"(a[2]), "r"(a[3]), "r"(b[0]), "r"(b[1]));
}
__device__ __forceinline__ void split_bf16(float f, unsigned short& hs, unsigned short& ls) {
    __nv_bfloat16 bh = __float2bfloat16_rn(f);
    float fh = __bfloat162float(bh);
    __nv_bfloat16 bl = __float2bfloat16_rn(f - fh);
    hs = __bfloat16_as_ushort(bh);
    ls = __bfloat16_as_ushort(bl);
}
__device__ __forceinline__ void split2pack(float f0, float f1, uint32_t& hi, uint32_t& lo) {
    unsigned short h0, l0, h1, l1;
    split_bf16(f0, h0, l0);
    split_bf16(f1, h1, l1);
    hi = (uint32_t)h0 | ((uint32_t)h1 << 16);
    lo = (uint32_t)l0 | ((uint32_t)l1 << 16);
}
__device__ __forceinline__ void cpa16(uint32_t s, const void* g) {
    asm volatile("cp.async.cg.shared.global [%0], [%1], 16;" :: "r"(s), "l"(g));
}
#define CP_COMMIT() asm volatile("cp.async.commit_group;")
#define CP_WAIT(n)  asm volatile("cp.async.wait_group %0;" :: "n"(n))

// ---------------- weight splitters ----------------
__global__ __launch_bounds__(256) void wsplit_kernel(
    const float* __restrict__ w, ushort_t* __restrict__ wh, ushort_t* __restrict__ wl)
{
    size_t i4 = ((size_t)blockIdx.x * 256 + threadIdx.x) * 4;
    float4 f = *(const float4*)(w + i4);
    uint32_t h0, l0, h1, l1;
    split2pack(f.x, f.y, h0, l0);
    split2pack(f.z, f.w, h1, l1);
    uint32_t* dh = (uint32_t*)(wh + i4);
    uint32_t* dl = (uint32_t*)(wl + i4);
    dh[0] = h0; dh[1] = h1; dl[0] = l0; dl[1] = l1;
}

// concatenate wq|wk|wv column-wise into [HH, 3HH] split planes
__global__ __launch_bounds__(256) void wsplit_qkv_kernel(
    const float* __restrict__ wq, const float* __restrict__ wk, const float* __restrict__ wv,
    ushort_t* __restrict__ wh, ushort_t* __restrict__ wl)
{
    size_t i4 = ((size_t)blockIdx.x * 256 + threadIdx.x) * 4;
    int r = (int)(i4 / H3);
    int c = (int)(i4 % H3);
    const float* src = (c < HH) ? (wq + (size_t)r * HH + c)
                     : (c < 2 * HH) ? (wk + (size_t)r * HH + (c - HH))
                     : (wv + (size_t)r * HH + (c - 2 * HH));
    float4 f = *(const float4*)src;
    uint32_t h0, l0, h1, l1;
    split2pack(f.x, f.y, h0, l0);
    split2pack(f.z, f.w, h1, l1);
    uint32_t* dh = (uint32_t*)(wh + i4);
    uint32_t* dl = (uint32_t*)(wl + i4);
    dh[0] = h0; dh[1] = h1; dl[0] = l0; dl[1] = l1;
}

// ---------------- LayerNorm -> split planes ----------------
__global__ __launch_bounds__(256) void ln_kernel(
    const float* __restrict__ x, const float* __restrict__ sc,
    const float* __restrict__ sh, ushort_t* __restrict__ yh, ushort_t* __restrict__ yl)
{
    const int N = HH;
    int row = blockIdx.x;
    int tid = threadIdx.x;
    const float* xr = x + (size_t)row * N;
    float2 vals[4];
    float s = 0.f, q = 0.f;
#pragma unroll
    for (int i = 0; i < 4; i++) {
        float2 v = *(const float2*)(xr + tid * 2 + i * 512);
        vals[i] = v;
        s += v.x + v.y; q += v.x * v.x + v.y * v.y;
    }
#pragma unroll
    for (int o = 16; o > 0; o >>= 1) {
        s += __shfl_xor_sync(0xffffffffu, s, o);
        q += __shfl_xor_sync(0xffffffffu, q, o);
    }
    __shared__ float ss[8], sq[8];
    __shared__ float smean, srstd;
    int warp = tid >> 5, lane = tid & 31;
    if (lane == 0) { ss[warp] = s; sq[warp] = q; }
    __syncthreads();
    if (tid == 0) {
        float S = 0.f, Q = 0.f;
#pragma unroll
        for (int i = 0; i < 8; i++) { S += ss[i]; Q += sq[i]; }
        float mean = S / N;
        float var  = Q / N - mean * mean;
        smean = mean;
        srstd = rsqrtf(var + 1e-5f);
    }
    __syncthreads();
    float mean = smean, rstd = srstd;
#pragma unroll
    for (int i = 0; i < 4; i++) {
        int c = tid * 2 + i * 512;
        float y0 = sc[c] * ((vals[i].x - mean) * rstd) + sh[c];
        float y1 = sc[c + 1] * ((vals[i].y - mean) * rstd) + sh[c + 1];
        uint32_t h, l;
        split2pack(y0, y1, h, l);
        *(uint32_t*)(yh + (size_t)row * N + c) = h;
        *(uint32_t*)(yl + (size_t)row * N + c) = l;
    }
}

// ---------------- pipelined bf16 GEMM (pre-split operands) -------------------
// EPI: 0 none, 1 +res, 2 gelu(+bias), 3 +bias+res
// OSPL: 0 fp32 out, 1 split planes out, 2 split planes out qkv (RS for cols<HH)
#define STAGES 3
#define A_ST 40
#define B_ST 136
#define A_TILE (128 * A_ST)
#define B_TILE (32 * B_ST)
#define STAGE_USH (2 * A_TILE + 2 * B_TILE)
#define GEMM_SMEM (STAGES * STAGE_USH * 2)

template <int EPI, int OSPL>
__global__ __launch_bounds__(256, 2) void bgemm_kernel(
    const ushort_t* __restrict__ Ahp, const ushort_t* __restrict__ Alp,
    const ushort_t* __restrict__ Bhp, const ushort_t* __restrict__ Blp,
    const float* __restrict__ bias, const float* __restrict__ res,
    float* __restrict__ C, ushort_t* __restrict__ Chp, ushort_t* __restrict__ Clp,
    int M, int N, int K, float oscale)
{
    extern __shared__ ushort_t sm[];
    int tid = threadIdx.x;
    int bm = blockIdx.y * 128;
    int bn = blockIdx.x * 128;
    int lane = tid & 31;
    int warp = tid >> 5;
    int wm = warp & 1;
    int wn = warp >> 1;

    const int nch = K / 32;

    auto issue = [&](int ch, int st) {
        int k0 = ch * 32;
        ushort_t* a_h = sm + st * STAGE_USH;
        ushort_t* a_l = a_h + A_TILE;
        ushort_t* b_h = a_l + A_TILE;
        ushort_t* b_l = b_h + B_TILE;
#pragma unroll
        for (int i = 0; i < 2; i++) {
            int lin = tid + i * 256;
            int r = lin >> 2, c8 = (lin & 3) * 8;
            cpa16(smem_u32(a_h + r * A_ST + c8), Ahp + (size_t)(bm + r) * K + k0 + c8);
            cpa16(smem_u32(a_l + r * A_ST + c8), Alp + (size_t)(bm + r) * K + k0 + c8);
            int br = lin >> 4, bc8 = (lin & 15) * 8;
            cpa16(smem_u32(b_h + br * B_ST + bc8), Bhp + (size_t)(k0 + br) * N + bn + bc8);
            cpa16(smem_u32(b_l + br * B_ST + bc8), Blp + (size_t)(k0 + br) * N + bn + bc8);
        }
    };

    float acc[4][4][4];
#pragma unroll
    for (int i = 0; i < 4; i++)
#pragma unroll
        for (int j = 0; j < 4; j++)
#pragma unroll
            for (int r = 0; r < 4; r++) acc[i][j][r] = 0.f;

#pragma unroll
    for (int s = 0; s < STAGES - 1; s++) { issue(s, s); CP_COMMIT(); }

    for (int ch = 0; ch < nch; ch++) {
        CP_WAIT(STAGES - 2);
        __syncthreads();

        if (ch + STAGES - 1 < nch) issue(ch + STAGES - 1, (ch + STAGES - 1) % STAGES);
        CP_COMMIT();

        int st = ch % STAGES;
        ushort_t* a_h = sm + st * STAGE_USH;
        ushort_t* a_l = a_h + A_TILE;
        ushort_t* b_h = a_l + A_TILE;
        ushort_t* b_l = b_h + B_TILE;

#pragma unroll
        for (int ks = 0; ks < 2; ks++) {
            // B fragments first (live across the mi loop)
            uint32_t b_hi[2][4], b_lo[2][4];
            int krow = ks * 16 + (lane & 15);
            int bcol = (lane >> 4) << 3;
#pragma unroll
            for (int np = 0; np < 2; np++) {
                int n0 = wn * 32 + np * 16 + bcol;
                ldsm_x4t(b_hi[np], smem_u32(b_h + krow * B_ST + n0));
                ldsm_x4t(b_lo[np], smem_u32(b_l + krow * B_ST + n0));
            }
            int row_base = wm * 64 + (lane & 15);
            int kh_a = ks * 16 + ((lane >> 4) << 3);
            // per-mi A fragments with short live ranges
#pragma unroll
            for (int mi = 0; mi < 4; mi++) {
                uint32_t a_hi[4], a_lo[4];
                ldsm_x4(a_hi, smem_u32(a_h + (row_base + mi * 16) * A_ST + kh_a));
                ldsm_x4(a_lo, smem_u32(a_l + (row_base + mi * 16) * A_ST + kh_a));
#pragma unroll
                for (int ni = 0; ni < 4; ni++) {
                    const uint32_t* bh = &b_hi[ni >> 1][(ni & 1) * 2];
                    const uint32_t* bl = &b_lo[ni >> 1][(ni & 1) * 2];
                    mma16816(acc[mi][ni], a_hi, bh);
                    mma16816(acc[mi][ni], a_hi, bl);
                    mma16816(acc[mi][ni], a_lo, bh);
                }
            }
        }
    }

    int g = lane >> 2, tq = lane & 3;
#pragma unroll
    for (int mi = 0; mi < 4; mi++) {
#pragma unroll
        for (int ni = 0; ni < 4; ni++) {
            int row0 = bm + wm * 64 + mi * 16 + g;
            int col0 = bn + wn * 32 + ni * 8 + tq * 2;
#pragma unroll
            for (int half = 0; half < 2; half++) {
                int row = row0 + half * 8;
                float v0 = acc[mi][ni][half * 2 + 0];
                float v1 = acc[mi][ni][half * 2 + 1];
                size_t idx = (size_t)row * N + col0;
                if (EPI == 1) { v0 += res[idx]; v1 += res[idx + 1]; }
                else if (EPI == 2) { v0 = gelu_tanh(v0 + bias[col0]); v1 = gelu_tanh(v1 + bias[col0 + 1]); }
                else if (EPI == 3) { v0 = v0 + bias[col0] + res[idx]; v1 = v1 + bias[col0 + 1] + res[idx + 1]; }
                if (OSPL) {
                    float sc = (OSPL == 2) ? ((col0 < HH) ? RS : 1.f) : oscale;
                    uint32_t hpk, lpk;
                    split2pack(v0 * sc, v1 * sc, hpk, lpk);
                    *(uint32_t*)(Chp + idx) = hpk;
                    *(uint32_t*)(Clp + idx) = lpk;
                } else {
                    float2 o; o.x = v0; o.y = v1;
                    *(float2*)(C + idx) = o;
                }
            }
        }
    }
}

// ---------------- flash attention (Q fragments hoisted to registers) --------
#define AST 136

__global__ __launch_bounds__(256, 1) void fattn_kernel(
    const ushort_t* __restrict__ QKVh, const ushort_t* __restrict__ QKVl,
    ushort_t* __restrict__ Ohp, ushort_t* __restrict__ Olp)
{
    extern __shared__ ushort_t smatt[];
    ushort_t* Qh = smatt;
    ushort_t* Ql = Qh + 128 * AST;
    ushort_t* KhA = Ql + 128 * AST;
    ushort_t* KlA = KhA + 2 * 64 * AST;
    ushort_t* VhA = KlA + 2 * 64 * AST;
    ushort_t* VlA = VhA + 2 * 64 * AST;

    int tid = threadIdx.x, lane = tid & 31, warp = tid >> 5;
    int bh = blockIdx.x;
    int b = bh >> 4, h = bh & 15;
    int qt = 15 - (int)blockIdx.y;

    size_t qoffg = ((size_t)(b * TT + qt * 128)) * H3 + h * HDIM;
    size_t koff  = ((size_t)(b * TT)) * H3 + HH + h * HDIM;
    size_t voff  = ((size_t)(b * TT)) * H3 + 2 * HH + h * HDIM;

#pragma unroll
    for (int i = 0; i < 8; i++) {
        int lin = tid + i * 256;
        int r = lin >> 4, c8 = (lin & 15) * 8;
        cpa16(smem_u32(Qh + r * AST + c8), QKVh + qoffg + (size_t)r * H3 + c8);
        cpa16(smem_u32(Ql + r * AST + c8), QKVl + qoffg + (size_t)r * H3 + c8);
    }
    CP_COMMIT();

    auto loadKV = [&](int blk, int bufI) {
        ushort_t* kh = KhA + bufI * 64 * AST;
        ushort_t* kl = KlA + bufI * 64 * AST;
        ushort_t* vh = VhA + bufI * 64 * AST;
        ushort_t* vl = VlA + bufI * 64 * AST;
        size_t kb = koff + (size_t)(blk * 64) * H3;
        size_t vb = voff + (size_t)(blk * 64) * H3;
#pragma unroll
        for (int i = 0; i < 4; i++) {
            int lin = tid + i * 256;
            int key = lin >> 4, c8 = (lin & 15) * 8;
            size_t stp = (size_t)key * H3 + c8;
            int so = key * AST + c8;
            cpa16(smem_u32(kh + so), QKVh + kb + stp);
            cpa16(smem_u32(kl + so), QKVl + kb + stp);
            cpa16(smem_u32(vh + so), QKVh + vb + stp);
            cpa16(smem_u32(vl + so), QKVl + vb + stp);
        }
    };

    loadKV(0, 0);
    CP_COMMIT();
    CP_WAIT(0);
    __syncthreads();

    // hoist Q fragments into registers (loop-invariant)
    uint32_t qa_hi[8][4], qa_lo[8][4];
#pragma unroll
    for (int ks = 0; ks < 8; ks++) {
        int qoff = (warp * 16 + (lane & 15)) * AST + ks * 16 + ((lane >> 4) << 3);
        ldsm_x4(qa_hi[ks], smem_u32(&Qh[qoff]));
        ldsm_x4(qa_lo[ks], smem_u32(&Ql[qoff]));
    }

    float o[16][4];
#pragma unroll
    for (int i = 0; i < 16; i++)
#pragma unroll
        for (int j = 0; j < 4; j++) o[i][j] = 0.f;

    float mrow0 = -1e30f, mrow1 = -1e30f;
    float lrow0 = 0.f, lrow1 = 0.f;

    int r0 = lane >> 2;
    int cbase = (lane & 3) * 2;
    int qrow0 = qt * 128 + warp * 16 + r0;
    int qrow1 = qrow0 + 8;
    int wmin = qt * 128 + warp * 16;

    const int nblocks = 2 * qt + 2;
    for (int kb = 0; kb < nblocks; kb++) {
        int buf = kb & 1;

        if (kb + 1 < nblocks) { loadKV(kb + 1, buf ^ 1); }
        CP_COMMIT();

        ushort_t* KhB = KhA + buf * 64 * AST;
        ushort_t* KlB = KlA + buf * 64 * AST;
        ushort_t* VhB = VhA + buf * 64 * AST;
        ushort_t* VlB = VlA + buf * 64 * AST;

        int kbase = kb * 64;
        bool live = (kbase <= wmin + 15);
        if (live) {
            float s[8][4];
#pragma unroll
            for (int i = 0; i < 8; i++)
#pragma unroll
                for (int j = 0; j < 4; j++) s[i][j] = 0.f;

#pragma unroll
            for (int ks = 0; ks < 8; ks++) {
                int nrow_off = ((lane >> 4) << 3) + (lane & 7);
                int kcol = ks * 16 + (((lane >> 3) & 1) << 3);
#pragma unroll
                for (int ntp = 0; ntp < 4; ntp++) {
                    uint32_t bhf[4], blf[4];
                    int koff2 = (ntp * 16 + nrow_off) * AST + kcol;
                    ldsm_x4(bhf, smem_u32(&KhB[koff2]));
                    ldsm_x4(blf, smem_u32(&KlB[koff2]));
                    mma16816(s[2 * ntp], qa_hi[ks], bhf);
                    mma16816(s[2 * ntp], qa_hi[ks], blf);
                    mma16816(s[2 * ntp], qa_lo[ks], bhf);
                    mma16816(s[2 * ntp + 1], qa_hi[ks], bhf + 2);
                    mma16816(s[2 * ntp + 1], qa_hi[ks], blf + 2);
                    mma16816(s[2 * ntp + 1], qa_lo[ks], bhf + 2);
                }
            }

            if (kbase + 63 > wmin) {
#pragma unroll
                for (int nt = 0; nt < 8; nt++) {
#pragma unroll
                    for (int j = 0; j < 2; j++) {
                        int col = kbase + nt * 8 + cbase + j;
                        if (col > qrow0) s[nt][j] = -1e30f;
                        if (col > qrow1) s[nt][2 + j] = -1e30f;
                    }
                }
            }

            float mx0 = -1e30f, mx1 = -1e30f;
#pragma unroll
            for (int nt = 0; nt < 8; nt++) {
                mx0 = fmaxf(mx0, fmaxf(s[nt][0], s[nt][1]));
                mx1 = fmaxf(mx1, fmaxf(s[nt][2], s[nt][3]));
            }
            mx0 = fmaxf(mx0, __shfl_xor_sync(0xffffffffu, mx0, 1));
            mx0 = fmaxf(mx0, __shfl_xor_sync(0xffffffffu, mx0, 2));
            mx1 = fmaxf(mx1, __shfl_xor_sync(0xffffffffu, mx1, 1));
            mx1 = fmaxf(mx1, __shfl_xor_sync(0xffffffffu, mx1, 2));
            float mn0 = fmaxf(mrow0, mx0), mn1 = fmaxf(mrow1, mx1);
            float c0 = __expf(mrow0 - mn0), c1 = __expf(mrow1 - mn1);
            mrow0 = mn0; mrow1 = mn1;
            float sum0 = 0.f, sum1 = 0.f;
#pragma unroll
            for (int nt = 0; nt < 8; nt++) {
                s[nt][0] = __expf(s[nt][0] - mn0); sum0 += s[nt][0];
                s[nt][1] = __expf(s[nt][1] - mn0); sum0 += s[nt][1];
                s[nt][2] = __expf(s[nt][2] - mn1); sum1 += s[nt][2];
                s[nt][3] = __expf(s[nt][3] - mn1); sum1 += s[nt][3];
            }
            sum0 += __shfl_xor_sync(0xffffffffu, sum0, 1);
            sum0 += __shfl_xor_sync(0xffffffffu, sum0, 2);
            sum1 += __shfl_xor_sync(0xffffffffu, sum1, 1);
            sum1 += __shfl_xor_sync(0xffffffffu, sum1, 2);
            lrow0 = lrow0 * c0 + sum0;
            lrow1 = lrow1 * c1 + sum1;
#pragma unroll
            for (int nt = 0; nt < 16; nt++) {
                o[nt][0] *= c0; o[nt][1] *= c0;
                o[nt][2] *= c1; o[nt][3] *= c1;
            }

#pragma unroll
            for (int ks2 = 0; ks2 < 4; ks2++) {
                uint32_t pah[4], pal[4];
                split2pack(s[2 * ks2][0], s[2 * ks2][1], pah[0], pal[0]);
                split2pack(s[2 * ks2][2], s[2 * ks2][3], pah[1], pal[1]);
                split2pack(s[2 * ks2 + 1][0], s[2 * ks2 + 1][1], pah[2], pal[2]);
                split2pack(s[2 * ks2 + 1][2], s[2 * ks2 + 1][3], pah[3], pal[3]);
                int vrow = ks2 * 16 + (lane & 15);
                int vcol_off = (lane >> 4) << 3;
#pragma unroll
                for (int ntp = 0; ntp < 8; ntp++) {
                    uint32_t vhf[4], vlf[4];
                    int voff2 = vrow * AST + ntp * 16 + vcol_off;
                    ldsm_x4t(vhf, smem_u32(&VhB[voff2]));
                    ldsm_x4t(vlf, smem_u32(&VlB[voff2]));
                    mma16816(o[2 * ntp], pah, vhf);
                    mma16816(o[2 * ntp], pah, vlf);
                    mma16816(o[2 * ntp], pal, vhf);
                    mma16816(o[2 * ntp + 1], pah, vhf + 2);
                    mma16816(o[2 * ntp + 1], pah, vlf + 2);
                    mma16816(o[2 * ntp + 1], pal, vhf + 2);
                }
            }
        }

        CP_WAIT(0);
        __syncthreads();
    }

    float inv0 = 1.f / lrow0, inv1 = 1.f / lrow1;
    size_t obase = ((size_t)(b * TT)) * HH + h * HDIM;
    int grow0 = qt * 128 + warp * 16 + r0;
#pragma unroll
    for (int nt = 0; nt < 16; nt++) {
        int col = nt * 8 + cbase;
        uint32_t hpk, lpk;
        split2pack(o[nt][0] * inv0, o[nt][1] * inv0, hpk, lpk);
        *(uint32_t*)(Ohp + obase + (size_t)grow0 * HH + col) = hpk;
        *(uint32_t*)(Olp + obase + (size_t)grow0 * HH + col) = lpk;
        split2pack(o[nt][2] * inv1, o[nt][3] * inv1, hpk, lpk);
        *(uint32_t*)(Ohp + obase + (size_t)(grow0 + 8) * HH + col) = hpk;
        *(uint32_t*)(Olp + obase + (size_t)(grow0 + 8) * HH + col) = lpk;
    }
}

// ---------------- launch ----------------------------------------------------
extern "C" void kernel_launch(void* const* d_in, const int* in_sizes, int n_in,
                              void* d_out, int out_size)
{
    const float* x   = (const float*)d_in[0];
    const float* wq  = (const float*)d_in[1];
    const float* wk  = (const float*)d_in[2];
    const float* wv  = (const float*)d_in[3];
    const float* wo  = (const float*)d_in[4];
    const float* ln1s = (const float*)d_in[5];
    const float* ln1b = (const float*)d_in[6];
    const float* ln2s = (const float*)d_in[7];
    const float* ln2b = (const float*)d_in[8];
    const float* w1  = (const float*)d_in[9];
    const float* b1  = (const float*)d_in[10];
    const float* w2  = (const float*)d_in[11];
    const float* b2  = (const float*)d_in[12];
    float* out = (float*)d_out;

    ushort_t *hh, *hl, *qkvh, *qkvl, *ath, *atl, *fh, *fl;
    ushort_t *wqkvh, *wqkvl, *woh, *wol, *w1h, *w1l, *w2h, *w2l;
    float *x1;
    cudaGetSymbolAddress((void**)&hh, g_h_hi);     cudaGetSymbolAddress((void**)&hl, g_h_lo);
    cudaGetSymbolAddress((void**)&qkvh, g_qkv_hi); cudaGetSymbolAddress((void**)&qkvl, g_qkv_lo);
    cudaGetSymbolAddress((void**)&ath, g_at_hi);   cudaGetSymbolAddress((void**)&atl, g_at_lo);
    cudaGetSymbolAddress((void**)&fh, g_f_hi);     cudaGetSymbolAddress((void**)&fl, g_f_lo);
    cudaGetSymbolAddress((void**)&wqkvh, g_wqkv_hi); cudaGetSymbolAddress((void**)&wqkvl, g_wqkv_lo);
    cudaGetSymbolAddress((void**)&woh, g_wo_hi);   cudaGetSymbolAddress((void**)&wol, g_wo_lo);
    cudaGetSymbolAddress((void**)&w1h, g_w1_hi);   cudaGetSymbolAddress((void**)&w1l, g_w1_lo);
    cudaGetSymbolAddress((void**)&w2h, g_w2_hi);   cudaGetSymbolAddress((void**)&w2l, g_w2_lo);
    cudaGetSymbolAddress((void**)&x1, g_x1);

    cudaFuncSetAttribute(bgemm_kernel<0,2>, cudaFuncAttributeMaxDynamicSharedMemorySize, GEMM_SMEM);
    cudaFuncSetAttribute(bgemm_kernel<1,0>, cudaFuncAttributeMaxDynamicSharedMemorySize, GEMM_SMEM);
    cudaFuncSetAttribute(bgemm_kernel<2,1>, cudaFuncAttributeMaxDynamicSharedMemorySize, GEMM_SMEM);
    cudaFuncSetAttribute(bgemm_kernel<3,0>, cudaFuncAttributeMaxDynamicSharedMemorySize, GEMM_SMEM);
    const int att_smem = (2 * 128 + 8 * 64) * AST * 2;
    cudaFuncSetAttribute(fattn_kernel, cudaFuncAttributeMaxDynamicSharedMemorySize, att_smem);

    dim3 gQKV(H3 / 128, MM / 128);   // 48 x 32
    dim3 gHH(HH / 128, MM / 128);
    dim3 gFF(FF / 128, MM / 128);
    dim3 blk(256);

    // side stream: wo/w1/w2 splits (consumed only after attention)
    cudaStream_t s1;
    cudaStreamCreateWithFlags(&s1, cudaStreamNonBlocking);
    cudaEvent_t e0, e1;
    cudaEventCreateWithFlags(&e0, cudaEventDisableTiming);
    cudaEventCreateWithFlags(&e1, cudaEventDisableTiming);

    cudaEventRecord(e0, 0);                 // fork from capture (legacy) stream
    cudaStreamWaitEvent(s1, e0, 0);
    wsplit_kernel<<<HH * HH / 1024, 256, 0, s1>>>(wo, woh, wol);
    wsplit_kernel<<<HH * FF / 1024, 256, 0, s1>>>(w1, w1h, w1l);
    wsplit_kernel<<<HH * FF / 1024, 256, 0, s1>>>(w2, w2h, w2l);
    cudaEventRecord(e1, s1);

    // main chain
    wsplit_qkv_kernel<<<HH * H3 / 1024, 256>>>(wq, wk, wv, wqkvh, wqkvl);
    ln_kernel<<<MM, 256>>>(x, ln1s, ln1b, hh, hl);
    bgemm_kernel<0,2><<<gQKV, blk, GEMM_SMEM>>>(hh, hl, wqkvh, wqkvl, nullptr, nullptr, nullptr, qkvh, qkvl, MM, H3, HH, 1.f);
    dim3 ga(BB * NHD, TT / 128);
    fattn_kernel<<<ga, 256, att_smem>>>(qkvh, qkvl, ath, atl);

    cudaStreamWaitEvent(0, e1, 0);          // join before first weight consumer
    bgemm_kernel<1,0><<<gHH, blk, GEMM_SMEM>>>(ath, atl, woh, wol, nullptr, x, x1, nullptr, nullptr, MM, HH, HH, 1.f);
    ln_kernel<<<MM, 256>>>(x1, ln2s, ln2b, hh, hl);
    bgemm_kernel<2,1><<<gFF, blk, GEMM_SMEM>>>(hh, hl, w1h, w1l, b1, nullptr, nullptr, fh, fl, MM, FF, HH, 1.f);
    bgemm_kernel<3,0><<<gHH, blk, GEMM_SMEM>>>(fh, fl, w2h, w2l, b2, x1, out, nullptr, nullptr, MM, HH, FF, 1.f);

    cudaEventDestroy(e0);
    cudaEventDestroy(e1);
    cudaStreamDestroy(s1);
}

// round 16
// speedup vs baseline: 1.0030x; 1.0030x over previous
#include <cuda_runtime.h>
#include <cuda_bf16.h>
#include <math.h>
#include <stdint.h>

// Problem constants
#define BB 2
#define TT 2048
#define HH 2048
#define NHD 16
#define HDIM 128
#define MM (BB*TT)      // 4096 token rows
#define FF (4*HH)       // 8192
#define H3 (3*HH)       // 6144

typedef unsigned short ushort_t;

// ---------------- scratch (device globals; allocation-free) ----------------
static __device__ ushort_t g_h_hi  [(size_t)MM*HH];
static __device__ ushort_t g_h_lo  [(size_t)MM*HH];
static __device__ ushort_t g_qkv_hi[(size_t)MM*H3];
static __device__ ushort_t g_qkv_lo[(size_t)MM*H3];
static __device__ ushort_t g_at_hi [(size_t)MM*HH];
static __device__ ushort_t g_at_lo [(size_t)MM*HH];
static __device__ ushort_t g_f_hi  [(size_t)MM*FF];
static __device__ ushort_t g_f_lo  [(size_t)MM*FF];
static __device__ float    g_x1    [(size_t)MM*HH];
// weight planes [K, N] row-major (B operand via ldmatrix.trans)
static __device__ ushort_t g_wqkv_hi[(size_t)HH*H3];
static __device__ ushort_t g_wqkv_lo[(size_t)HH*H3];
static __device__ ushort_t g_wo_hi[(size_t)HH*HH];
static __device__ ushort_t g_wo_lo[(size_t)HH*HH];
static __device__ ushort_t g_w1_hi[(size_t)HH*FF];
static __device__ ushort_t g_w1_lo[(size_t)HH*FF];
static __device__ ushort_t g_w2_hi[(size_t)HH*FF];
static __device__ ushort_t g_w2_lo[(size_t)HH*FF];

#define RS 0.08838834764831845f   // 1/sqrt(128)

// ---------------- helpers ----------------
__device__ __forceinline__ float gelu_tanh(float x) {
    float x3 = x * x * x;
    return 0.5f * x * (1.f + tanhf(0.7978845608028654f * (x + 0.044715f * x3)));
}
__device__ __forceinline__ uint32_t smem_u32(const void* p) {
    return (uint32_t)__cvta_generic_to_shared(p);
}
__device__ __forceinline__ void ldsm_x4(uint32_t* d, uint32_t addr) {
    asm volatile("ldmatrix.sync.aligned.m8n8.x4.shared.b16 {%0,%1,%2,%3}, [%4];"
                 : "=r"(d[0]), "=r"(d[1]), "=r"(d[2]), "=r"(d[3]) : "r"(addr));
}
__device__ __forceinline__ void ldsm_x4t(uint32_t* d, uint32_t addr) {
    asm volatile("ldmatrix.sync.aligned.m8n8.x4.trans.shared.b16 {%0,%1,%2,%3}, [%4];"
                 : "=r"(d[0]), "=r"(d[1]), "=r"(d[2]), "=r"(d[3]) : "r"(addr));
}
__device__ __forceinline__ void mma16816(float* c, const uint32_t* a, const uint32_t* b) {
    asm volatile("mma.sync.aligned.m16n8k16.row.col.f32.bf16.bf16.f32 "
                 "{%0,%1,%2,%3}, {%4,%5,%6,%7}, {%8,%9}, {%0,%1,%2,%3};"
                 : "+f"(c[0]), "+f"(c[1]), "+f"(c[2]), "+f"(c[3])
                 : "r"(a[0]), "r"(a[1]), "r"(a[2]), "r"(a[3]), "r"(b[0]), "r"(b[1]));
}
__device__ __forceinline__ void split_bf16(float f, unsigned short& hs, unsigned short& ls) {
    __nv_bfloat16 bh = __float2bfloat16_rn(f);
    float fh = __bfloat162float(bh);
    __nv_bfloat16 bl = __float2bfloat16_rn(f - fh);
    hs = __bfloat16_as_ushort(bh);
    ls = __bfloat16_as_ushort(bl);
}
__device__ __forceinline__ void split2pack(float f0, float f1, uint32_t& hi, uint32_t& lo) {
    unsigned short h0, l0, h1, l1;
    split_bf16(f0, h0, l0);
    split_bf16(f1, h1, l1);
    hi = (uint32_t)h0 | ((uint32_t)h1 << 16);
    lo = (uint32_t)l0 | ((uint32_t)l1 << 16);
}
__device__ __forceinline__ void cpa16(uint32_t s, const void* g) {
    asm volatile("cp.async.cg.shared.global [%0], [%1], 16;" :: "r"(s), "l"(g));
}
#define CP_COMMIT() asm volatile("cp.async.commit_group;")
#define CP_WAIT(n)  asm volatile("cp.async.wait_group %0;" :: "n"(n))

// ---------------- weight splitters ----------------
__global__ __launch_bounds__(256) void wsplit_kernel(
    const float* __restrict__ w, ushort_t* __restrict__ wh, ushort_t* __restrict__ wl)
{
    size_t i4 = ((size_t)blockIdx.x * 256 + threadIdx.x) * 4;
    float4 f = *(const float4*)(w + i4);
    uint32_t h0, l0, h1, l1;
    split2pack(f.x, f.y, h0, l0);
    split2pack(f.z, f.w, h1, l1);
    uint32_t* dh = (uint32_t*)(wh + i4);
    uint32_t* dl = (uint32_t*)(wl + i4);
    dh[0] = h0; dh[1] = h1; dl[0] = l0; dl[1] = l1;
}

// concatenate wq|wk|wv column-wise into [HH, 3HH] split planes
__global__ __launch_bounds__(256) void wsplit_qkv_kernel(
    const float* __restrict__ wq, const float* __restrict__ wk, const float* __restrict__ wv,
    ushort_t* __restrict__ wh, ushort_t* __restrict__ wl)
{
    size_t i4 = ((size_t)blockIdx.x * 256 + threadIdx.x) * 4;
    int r = (int)(i4 / H3);
    int c = (int)(i4 % H3);
    const float* src = (c < HH) ? (wq + (size_t)r * HH + c)
                     : (c < 2 * HH) ? (wk + (size_t)r * HH + (c - HH))
                     : (wv + (size_t)r * HH + (c - 2 * HH));
    float4 f = *(const float4*)src;
    uint32_t h0, l0, h1, l1;
    split2pack(f.x, f.y, h0, l0);
    split2pack(f.z, f.w, h1, l1);
    uint32_t* dh = (uint32_t*)(wh + i4);
    uint32_t* dl = (uint32_t*)(wl + i4);
    dh[0] = h0; dh[1] = h1; dl[0] = l0; dl[1] = l1;
}

// ---------------- LayerNorm -> split planes ----------------
__global__ __launch_bounds__(256) void ln_kernel(
    const float* __restrict__ x, const float* __restrict__ sc,
    const float* __restrict__ sh, ushort_t* __restrict__ yh, ushort_t* __restrict__ yl)
{
    const int N = HH;
    int row = blockIdx.x;
    int tid = threadIdx.x;
    const float* xr = x + (size_t)row * N;
    float2 vals[4];
    float s = 0.f, q = 0.f;
#pragma unroll
    for (int i = 0; i < 4; i++) {
        float2 v = *(const float2*)(xr + tid * 2 + i * 512);
        vals[i] = v;
        s += v.x + v.y; q += v.x * v.x + v.y * v.y;
    }
#pragma unroll
    for (int o = 16; o > 0; o >>= 1) {
        s += __shfl_xor_sync(0xffffffffu, s, o);
        q += __shfl_xor_sync(0xffffffffu, q, o);
    }
    __shared__ float ss[8], sq[8];
    __shared__ float smean, srstd;
    int warp = tid >> 5, lane = tid & 31;
    if (lane == 0) { ss[warp] = s; sq[warp] = q; }
    __syncthreads();
    if (tid == 0) {
        float S = 0.f, Q = 0.f;
#pragma unroll
        for (int i = 0; i < 8; i++) { S += ss[i]; Q += sq[i]; }
        float mean = S / N;
        float var  = Q / N - mean * mean;
        smean = mean;
        srstd = rsqrtf(var + 1e-5f);
    }
    __syncthreads();
    float mean = smean, rstd = srstd;
#pragma unroll
    for (int i = 0; i < 4; i++) {
        int c = tid * 2 + i * 512;
        float y0 = sc[c] * ((vals[i].x - mean) * rstd) + sh[c];
        float y1 = sc[c + 1] * ((vals[i].y - mean) * rstd) + sh[c + 1];
        uint32_t h, l;
        split2pack(y0, y1, h, l);
        *(uint32_t*)(yh + (size_t)row * N + c) = h;
        *(uint32_t*)(yl + (size_t)row * N + c) = l;
    }
}

// ---------------- pipelined bf16 GEMM (pre-split operands) -------------------
// EPI: 0 none, 1 +res, 2 gelu(+bias), 3 +bias+res
// OSPL: 0 fp32 out, 1 split planes out, 2 split planes out qkv (RS for cols<HH)
#define STAGES 3
#define A_ST 40
#define B_ST 136
#define A_TILE (128 * A_ST)
#define B_TILE (32 * B_ST)
#define STAGE_USH (2 * A_TILE + 2 * B_TILE)
#define GEMM_SMEM (STAGES * STAGE_USH * 2)

template <int EPI, int OSPL>
__global__ __launch_bounds__(256, 2) void bgemm_kernel(
    const ushort_t* __restrict__ Ahp, const ushort_t* __restrict__ Alp,
    const ushort_t* __restrict__ Bhp, const ushort_t* __restrict__ Blp,
    const float* __restrict__ bias, const float* __restrict__ res,
    float* __restrict__ C, ushort_t* __restrict__ Chp, ushort_t* __restrict__ Clp,
    int M, int N, int K, float oscale)
{
    extern __shared__ ushort_t sm[];
    int tid = threadIdx.x;
    int bm = blockIdx.y * 128;
    int bn = blockIdx.x * 128;
    int lane = tid & 31;
    int warp = tid >> 5;
    int wm = warp & 1;
    int wn = warp >> 1;

    const int nch = K / 32;

    auto issue = [&](int ch, int st) {
        int k0 = ch * 32;
        ushort_t* a_h = sm + st * STAGE_USH;
        ushort_t* a_l = a_h + A_TILE;
        ushort_t* b_h = a_l + A_TILE;
        ushort_t* b_l = b_h + B_TILE;
#pragma unroll
        for (int i = 0; i < 2; i++) {
            int lin = tid + i * 256;
            int r = lin >> 2, c8 = (lin & 3) * 8;
            cpa16(smem_u32(a_h + r * A_ST + c8), Ahp + (size_t)(bm + r) * K + k0 + c8);
            cpa16(smem_u32(a_l + r * A_ST + c8), Alp + (size_t)(bm + r) * K + k0 + c8);
            int br = lin >> 4, bc8 = (lin & 15) * 8;
            cpa16(smem_u32(b_h + br * B_ST + bc8), Bhp + (size_t)(k0 + br) * N + bn + bc8);
            cpa16(smem_u32(b_l + br * B_ST + bc8), Blp + (size_t)(k0 + br) * N + bn + bc8);
        }
    };

    float acc[4][4][4];
#pragma unroll
    for (int i = 0; i < 4; i++)
#pragma unroll
        for (int j = 0; j < 4; j++)
#pragma unroll
            for (int r = 0; r < 4; r++) acc[i][j][r] = 0.f;

#pragma unroll
    for (int s = 0; s < STAGES - 1; s++) { issue(s, s); CP_COMMIT(); }

    for (int ch = 0; ch < nch; ch++) {
        CP_WAIT(STAGES - 2);
        __syncthreads();

        if (ch + STAGES - 1 < nch) issue(ch + STAGES - 1, (ch + STAGES - 1) % STAGES);
        CP_COMMIT();

        int st = ch % STAGES;
        ushort_t* a_h = sm + st * STAGE_USH;
        ushort_t* a_l = a_h + A_TILE;
        ushort_t* b_h = a_l + A_TILE;
        ushort_t* b_l = b_h + B_TILE;

#pragma unroll
        for (int ks = 0; ks < 2; ks++) {
            // B fragments first (live across the mi loop)
            uint32_t b_hi[2][4], b_lo[2][4];
            int krow = ks * 16 + (lane & 15);
            int bcol = (lane >> 4) << 3;
#pragma unroll
            for (int np = 0; np < 2; np++) {
                int n0 = wn * 32 + np * 16 + bcol;
                ldsm_x4t(b_hi[np], smem_u32(b_h + krow * B_ST + n0));
                ldsm_x4t(b_lo[np], smem_u32(b_l + krow * B_ST + n0));
            }
            int row_base = wm * 64 + (lane & 15);
            int kh_a = ks * 16 + ((lane >> 4) << 3);
            // per-mi A fragments with short live ranges
#pragma unroll
            for (int mi = 0; mi < 4; mi++) {
                uint32_t a_hi[4], a_lo[4];
                ldsm_x4(a_hi, smem_u32(a_h + (row_base + mi * 16) * A_ST + kh_a));
                ldsm_x4(a_lo, smem_u32(a_l + (row_base + mi * 16) * A_ST + kh_a));
#pragma unroll
                for (int ni = 0; ni < 4; ni++) {
                    const uint32_t* bh = &b_hi[ni >> 1][(ni & 1) * 2];
                    const uint32_t* bl = &b_lo[ni >> 1][(ni & 1) * 2];
                    mma16816(acc[mi][ni], a_hi, bh);
                    mma16816(acc[mi][ni], a_hi, bl);
                    mma16816(acc[mi][ni], a_lo, bh);
                }
            }
        }
    }

    int g = lane >> 2, tq = lane & 3;
#pragma unroll
    for (int mi = 0; mi < 4; mi++) {
#pragma unroll
        for (int ni = 0; ni < 4; ni++) {
            int row0 = bm + wm * 64 + mi * 16 + g;
            int col0 = bn + wn * 32 + ni * 8 + tq * 2;
#pragma unroll
            for (int half = 0; half < 2; half++) {
                int row = row0 + half * 8;
                float v0 = acc[mi][ni][half * 2 + 0];
                float v1 = acc[mi][ni][half * 2 + 1];
                size_t idx = (size_t)row * N + col0;
                if (EPI == 1) { v0 += res[idx]; v1 += res[idx + 1]; }
                else if (EPI == 2) { v0 = gelu_tanh(v0 + bias[col0]); v1 = gelu_tanh(v1 + bias[col0 + 1]); }
                else if (EPI == 3) { v0 = v0 + bias[col0] + res[idx]; v1 = v1 + bias[col0 + 1] + res[idx + 1]; }
                if (OSPL) {
                    float sc = (OSPL == 2) ? ((col0 < HH) ? RS : 1.f) : oscale;
                    uint32_t hpk, lpk;
                    split2pack(v0 * sc, v1 * sc, hpk, lpk);
                    *(uint32_t*)(Chp + idx) = hpk;
                    *(uint32_t*)(Clp + idx) = lpk;
                } else {
                    float2 o; o.x = v0; o.y = v1;
                    *(float2*)(C + idx) = o;
                }
            }
        }
    }
}

// ---------------- flash attention: 128-thr CTA, 64-q tile, 32-key blocks ----
// occ 2: two CTAs per SM interleave MMA bursts with softmax chains.
#define AST 136
// smem: Q 64 rows (hi+lo) + KV 32-key double buffer (K/V x hi/lo x 2)
#define ATT_SMEM ((128 + 8 * 32) * AST * 2)

__global__ __launch_bounds__(128, 2) void fattn_kernel(
    const ushort_t* __restrict__ QKVh, const ushort_t* __restrict__ QKVl,
    ushort_t* __restrict__ Ohp, ushort_t* __restrict__ Olp)
{
    extern __shared__ ushort_t smatt[];
    ushort_t* Qh = smatt;
    ushort_t* Ql = Qh + 64 * AST;
    ushort_t* KhA = Ql + 64 * AST;          // [2][32][AST]
    ushort_t* KlA = KhA + 2 * 32 * AST;
    ushort_t* VhA = KlA + 2 * 32 * AST;
    ushort_t* VlA = VhA + 2 * 32 * AST;

    int tid = threadIdx.x, lane = tid & 31, warp = tid >> 5;   // 4 warps
    int bh = blockIdx.x;
    int b = bh >> 4, h = bh & 15;
    int qt = 31 - (int)blockIdx.y;          // 64-row q tiles, heavy first

    size_t qoffg = ((size_t)(b * TT + qt * 64)) * H3 + h * HDIM;
    size_t koff  = ((size_t)(b * TT)) * H3 + HH + h * HDIM;
    size_t voff  = ((size_t)(b * TT)) * H3 + 2 * HH + h * HDIM;

    // Q tile: 64 rows, hi+lo planes
#pragma unroll
    for (int i = 0; i < 8; i++) {
        int lin = tid + i * 128;            // 0..1023
        int r = lin >> 4, c8 = (lin & 15) * 8;
        cpa16(smem_u32(Qh + r * AST + c8), QKVh + qoffg + (size_t)r * H3 + c8);
        cpa16(smem_u32(Ql + r * AST + c8), QKVl + qoffg + (size_t)r * H3 + c8);
    }
    CP_COMMIT();

    auto loadKV = [&](int blk, int bufI) {   // blk in 32-key units
        ushort_t* kh = KhA + bufI * 32 * AST;
        ushort_t* kl = KlA + bufI * 32 * AST;
        ushort_t* vh = VhA + bufI * 32 * AST;
        ushort_t* vl = VlA + bufI * 32 * AST;
        size_t kb = koff + (size_t)(blk * 32) * H3;
        size_t vb = voff + (size_t)(blk * 32) * H3;
#pragma unroll
        for (int i = 0; i < 4; i++) {
            int lin = tid + i * 128;        // 0..511
            int key = lin >> 4, c8 = (lin & 15) * 8;
            size_t stp = (size_t)key * H3 + c8;
            int so = key * AST + c8;
            cpa16(smem_u32(kh + so), QKVh + kb + stp);
            cpa16(smem_u32(kl + so), QKVl + kb + stp);
            cpa16(smem_u32(vh + so), QKVh + vb + stp);
            cpa16(smem_u32(vl + so), QKVl + vb + stp);
        }
    };

    loadKV(0, 0);
    CP_COMMIT();
    CP_WAIT(0);
    __syncthreads();

    // hoist Q fragments (8 ksteps x hi/lo) — 128 regs budget is fine at occ 2
    uint32_t qa_hi[8][4], qa_lo[8][4];
#pragma unroll
    for (int ks = 0; ks < 8; ks++) {
        int qoff = (warp * 16 + (lane & 15)) * AST + ks * 16 + ((lane >> 4) << 3);
        ldsm_x4(qa_hi[ks], smem_u32(&Qh[qoff]));
        ldsm_x4(qa_lo[ks], smem_u32(&Ql[qoff]));
    }

    float o[16][4];
#pragma unroll
    for (int i = 0; i < 16; i++)
#pragma unroll
        for (int j = 0; j < 4; j++) o[i][j] = 0.f;

    float mrow0 = -1e30f, mrow1 = -1e30f;
    float lrow0 = 0.f, lrow1 = 0.f;

    int r0 = lane >> 2;
    int cbase = (lane & 3) * 2;
    int qrow0 = qt * 64 + warp * 16 + r0;
    int qrow1 = qrow0 + 8;
    int wmin = qt * 64 + warp * 16;

    const int nblocks = 2 * qt + 2;         // 32-key blocks
    for (int kb = 0; kb < nblocks; kb++) {
        int buf = kb & 1;

        if (kb + 1 < nblocks) { loadKV(kb + 1, buf ^ 1); }
        CP_COMMIT();

        ushort_t* KhB = KhA + buf * 32 * AST;
        ushort_t* KlB = KlA + buf * 32 * AST;
        ushort_t* VhB = VhA + buf * 32 * AST;
        ushort_t* VlB = VlA + buf * 32 * AST;

        int kbase = kb * 32;
        bool live = (kbase <= wmin + 15);
        if (live) {
            float s[4][4];
#pragma unroll
            for (int i = 0; i < 4; i++)
#pragma unroll
                for (int j = 0; j < 4; j++) s[i][j] = 0.f;

#pragma unroll
            for (int ks = 0; ks < 8; ks++) {
                int nrow_off = ((lane >> 4) << 3) + (lane & 7);
                int kcol = ks * 16 + (((lane >> 3) & 1) << 3);
#pragma unroll
                for (int ntp = 0; ntp < 2; ntp++) {   // 32 keys = 2 x 16
                    uint32_t bhf[4], blf[4];
                    int koff2 = (ntp * 16 + nrow_off) * AST + kcol;
                    ldsm_x4(bhf, smem_u32(&KhB[koff2]));
                    ldsm_x4(blf, smem_u32(&KlB[koff2]));
                    mma16816(s[2 * ntp], qa_hi[ks], bhf);
                    mma16816(s[2 * ntp], qa_hi[ks], blf);
                    mma16816(s[2 * ntp], qa_lo[ks], bhf);
                    mma16816(s[2 * ntp + 1], qa_hi[ks], bhf + 2);
                    mma16816(s[2 * ntp + 1], qa_hi[ks], blf + 2);
                    mma16816(s[2 * ntp + 1], qa_lo[ks], bhf + 2);
                }
            }

            if (kbase + 31 > wmin) {
#pragma unroll
                for (int nt = 0; nt < 4; nt++) {
#pragma unroll
                    for (int j = 0; j < 2; j++) {
                        int col = kbase + nt * 8 + cbase + j;
                        if (col > qrow0) s[nt][j] = -1e30f;
                        if (col > qrow1) s[nt][2 + j] = -1e30f;
                    }
                }
            }

            float mx0 = -1e30f, mx1 = -1e30f;
#pragma unroll
            for (int nt = 0; nt < 4; nt++) {
                mx0 = fmaxf(mx0, fmaxf(s[nt][0], s[nt][1]));
                mx1 = fmaxf(mx1, fmaxf(s[nt][2], s[nt][3]));
            }
            mx0 = fmaxf(mx0, __shfl_xor_sync(0xffffffffu, mx0, 1));
            mx0 = fmaxf(mx0, __shfl_xor_sync(0xffffffffu, mx0, 2));
            mx1 = fmaxf(mx1, __shfl_xor_sync(0xffffffffu, mx1, 1));
            mx1 = fmaxf(mx1, __shfl_xor_sync(0xffffffffu, mx1, 2));
            float mn0 = fmaxf(mrow0, mx0), mn1 = fmaxf(mrow1, mx1);
            float c0 = __expf(mrow0 - mn0), c1 = __expf(mrow1 - mn1);
            mrow0 = mn0; mrow1 = mn1;
            float sum0 = 0.f, sum1 = 0.f;
#pragma unroll
            for (int nt = 0; nt < 4; nt++) {
                s[nt][0] = __expf(s[nt][0] - mn0); sum0 += s[nt][0];
                s[nt][1] = __expf(s[nt][1] - mn0); sum0 += s[nt][1];
                s[nt][2] = __expf(s[nt][2] - mn1); sum1 += s[nt][2];
                s[nt][3] = __expf(s[nt][3] - mn1); sum1 += s[nt][3];
            }
            sum0 += __shfl_xor_sync(0xffffffffu, sum0, 1);
            sum0 += __shfl_xor_sync(0xffffffffu, sum0, 2);
            sum1 += __shfl_xor_sync(0xffffffffu, sum1, 1);
            sum1 += __shfl_xor_sync(0xffffffffu, sum1, 2);
            lrow0 = lrow0 * c0 + sum0;
            lrow1 = lrow1 * c1 + sum1;
#pragma unroll
            for (int nt = 0; nt < 16; nt++) {
                o[nt][0] *= c0; o[nt][1] *= c0;
                o[nt][2] *= c1; o[nt][3] *= c1;
            }

            // O += P V  (32 keys = 2 ksteps of 16)
#pragma unroll
            for (int ks2 = 0; ks2 < 2; ks2++) {
                uint32_t pah[4], pal[4];
                split2pack(s[2 * ks2][0], s[2 * ks2][1], pah[0], pal[0]);
                split2pack(s[2 * ks2][2], s[2 * ks2][3], pah[1], pal[1]);
                split2pack(s[2 * ks2 + 1][0], s[2 * ks2 + 1][1], pah[2], pal[2]);
                split2pack(s[2 * ks2 + 1][2], s[2 * ks2 + 1][3], pah[3], pal[3]);
                int vrow = ks2 * 16 + (lane & 15);
                int vcol_off = (lane >> 4) << 3;
#pragma unroll
                for (int ntp = 0; ntp < 8; ntp++) {
                    uint32_t vhf[4], vlf[4];
                    int voff2 = vrow * AST + ntp * 16 + vcol_off;
                    ldsm_x4t(vhf, smem_u32(&VhB[voff2]));
                    ldsm_x4t(vlf, smem_u32(&VlB[voff2]));
                    mma16816(o[2 * ntp], pah, vhf);
                    mma16816(o[2 * ntp], pah, vlf);
                    mma16816(o[2 * ntp], pal, vhf);
                    mma16816(o[2 * ntp + 1], pah, vhf + 2);
                    mma16816(o[2 * ntp + 1], pah, vlf + 2);
                    mma16816(o[2 * ntp + 1], pal, vhf + 2);
                }
            }
        }

        CP_WAIT(0);
        __syncthreads();
    }

    float inv0 = 1.f / lrow0, inv1 = 1.f / lrow1;
    size_t obase = ((size_t)(b * TT)) * HH + h * HDIM;
    int grow0 = qt * 64 + warp * 16 + r0;
#pragma unroll
    for (int nt = 0; nt < 16; nt++) {
        int col = nt * 8 + cbase;
        uint32_t hpk, lpk;
        split2pack(o[nt][0] * inv0, o[nt][1] * inv0, hpk, lpk);
        *(uint32_t*)(Ohp + obase + (size_t)grow0 * HH + col) = hpk;
        *(uint32_t*)(Olp + obase + (size_t)grow0 * HH + col) = lpk;
        split2pack(o[nt][2] * inv1, o[nt][3] * inv1, hpk, lpk);
        *(uint32_t*)(Ohp + obase + (size_t)(grow0 + 8) * HH + col) = hpk;
        *(uint32_t*)(Olp + obase + (size_t)(grow0 + 8) * HH + col) = lpk;
    }
}

// ---------------- launch ----------------------------------------------------
extern "C" void kernel_launch(void* const* d_in, const int* in_sizes, int n_in,
                              void* d_out, int out_size)
{
    const float* x   = (const float*)d_in[0];
    const float* wq  = (const float*)d_in[1];
    const float* wk  = (const float*)d_in[2];
    const float* wv  = (const float*)d_in[3];
    const float* wo  = (const float*)d_in[4];
    const float* ln1s = (const float*)d_in[5];
    const float* ln1b = (const float*)d_in[6];
    const float* ln2s = (const float*)d_in[7];
    const float* ln2b = (const float*)d_in[8];
    const float* w1  = (const float*)d_in[9];
    const float* b1  = (const float*)d_in[10];
    const float* w2  = (const float*)d_in[11];
    const float* b2  = (const float*)d_in[12];
    float* out = (float*)d_out;

    ushort_t *hh, *hl, *qkvh, *qkvl, *ath, *atl, *fh, *fl;
    ushort_t *wqkvh, *wqkvl, *woh, *wol, *w1h, *w1l, *w2h, *w2l;
    float *x1;
    cudaGetSymbolAddress((void**)&hh, g_h_hi);     cudaGetSymbolAddress((void**)&hl, g_h_lo);
    cudaGetSymbolAddress((void**)&qkvh, g_qkv_hi); cudaGetSymbolAddress((void**)&qkvl, g_qkv_lo);
    cudaGetSymbolAddress((void**)&ath, g_at_hi);   cudaGetSymbolAddress((void**)&atl, g_at_lo);
    cudaGetSymbolAddress((void**)&fh, g_f_hi);     cudaGetSymbolAddress((void**)&fl, g_f_lo);
    cudaGetSymbolAddress((void**)&wqkvh, g_wqkv_hi); cudaGetSymbolAddress((void**)&wqkvl, g_wqkv_lo);
    cudaGetSymbolAddress((void**)&woh, g_wo_hi);   cudaGetSymbolAddress((void**)&wol, g_wo_lo);
    cudaGetSymbolAddress((void**)&w1h, g_w1_hi);   cudaGetSymbolAddress((void**)&w1l, g_w1_lo);
    cudaGetSymbolAddress((void**)&w2h, g_w2_hi);   cudaGetSymbolAddress((void**)&w2l, g_w2_lo);
    cudaGetSymbolAddress((void**)&x1, g_x1);

    cudaFuncSetAttribute(bgemm_kernel<0,2>, cudaFuncAttributeMaxDynamicSharedMemorySize, GEMM_SMEM);
    cudaFuncSetAttribute(bgemm_kernel<1,0>, cudaFuncAttributeMaxDynamicSharedMemorySize, GEMM_SMEM);
    cudaFuncSetAttribute(bgemm_kernel<2,1>, cudaFuncAttributeMaxDynamicSharedMemorySize, GEMM_SMEM);
    cudaFuncSetAttribute(bgemm_kernel<3,0>, cudaFuncAttributeMaxDynamicSharedMemorySize, GEMM_SMEM);
    cudaFuncSetAttribute(fattn_kernel, cudaFuncAttributeMaxDynamicSharedMemorySize, ATT_SMEM);

    dim3 gQKV(H3 / 128, MM / 128);   // 48 x 32
    dim3 gHH(HH / 128, MM / 128);
    dim3 gFF(FF / 128, MM / 128);
    dim3 blk(256);

    // side stream: wo/w1/w2 splits (consumed only after attention)
    cudaStream_t s1;
    cudaStreamCreateWithFlags(&s1, cudaStreamNonBlocking);
    cudaEvent_t e0, e1;
    cudaEventCreateWithFlags(&e0, cudaEventDisableTiming);
    cudaEventCreateWithFlags(&e1, cudaEventDisableTiming);

    cudaEventRecord(e0, 0);                 // fork from capture (legacy) stream
    cudaStreamWaitEvent(s1, e0, 0);
    wsplit_kernel<<<HH * HH / 1024, 256, 0, s1>>>(wo, woh, wol);
    wsplit_kernel<<<HH * FF / 1024, 256, 0, s1>>>(w1, w1h, w1l);
    wsplit_kernel<<<HH * FF / 1024, 256, 0, s1>>>(w2, w2h, w2l);
    cudaEventRecord(e1, s1);

    // main chain
    wsplit_qkv_kernel<<<HH * H3 / 1024, 256>>>(wq, wk, wv, wqkvh, wqkvl);
    ln_kernel<<<MM, 256>>>(x, ln1s, ln1b, hh, hl);
    bgemm_kernel<0,2><<<gQKV, blk, GEMM_SMEM>>>(hh, hl, wqkvh, wqkvl, nullptr, nullptr, nullptr, qkvh, qkvl, MM, H3, HH, 1.f);
    dim3 ga(BB * NHD, TT / 64);             // 32 x 32 = 1024 CTAs
    fattn_kernel<<<ga, 128, ATT_SMEM>>>(qkvh, qkvl, ath, atl);

    cudaStreamWaitEvent(0, e1, 0);          // join before first weight consumer
    bgemm_kernel<1,0><<<gHH, blk, GEMM_SMEM>>>(ath, atl, woh, wol, nullptr, x, x1, nullptr, nullptr, MM, HH, HH, 1.f);
    ln_kernel<<<MM, 256>>>(x1, ln2s, ln2b, hh, hl);
    bgemm_kernel<2,1><<<gFF, blk, GEMM_SMEM>>>(hh, hl, w1h, w1l, b1, nullptr, nullptr, fh, fl, MM, FF, HH, 1.f);
    bgemm_kernel<3,0><<<gHH, blk, GEMM_SMEM>>>(fh, fl, w2h, w2l, b2, x1, out, nullptr, nullptr, MM, HH, FF, 1.f);

    cudaEventDestroy(e0);
    cudaEventDestroy(e1);
    cudaStreamDestroy(s1);
}